// round 13
// baseline (speedup 1.0000x reference)
#include <cuda_runtime.h>
#include <cstddef>
#include <cstdint>

// Problem constants (fixed by setup_inputs)
#define RB   12
#define LB   32
#define MB   16
#define HHB  32
#define HFB  64
#define EB   132
#define BTOT 64
#define NB_PER 8
#define NGROUP (BTOT/NB_PER)
#define NBLOCKS (NGROUP*RB)   // 96 blocks = 8 clusters of 12
#define NTHREADS 256          // 8 warps = 4 teams of 2, each team: 2 batches

struct __align__(16) SmemLayout {
    unsigned long long mbar[NB_PER][2];   // per-batch-chain mbarriers (count 22)
    float mw2[176*36];     // [(slot*16+m)][k] stride 36 (post means)
    float mb [176];
    float Cw [352*36];     // fused inc matrix [(slot*32+l)][k] stride 36
    float bincS[32];
    float gsw2[32*36];
    float gcw2[32*36];
    float gsb[32];
    float lw2[64*68];      // [o][i0..63] stride 68
    float lbS[64];
    float ow2[32*68];      // [l][hf]
    float obS[32];
    float wih2[96*36];
    float whh2[96*36];
    float bihS[96];
    float bhhS[96];
    // activations
    float zsD [3][NB_PER][RB][LB];   // triple-buffered exchanged z
    float incD[3][NB_PER][LB];
    float hbufT[NB_PER][HFB];
    float hgS [NB_PER][HHB];
    int   elist[12];
    int   slist[12];
};

__device__ __forceinline__ float fsig(float x) { return 1.0f / (1.0f + __expf(-x)); }

__device__ __forceinline__ uint32_t smem_u32(const void* p) {
    uint32_t a;
    asm("{ .reg .u64 t; cvta.to.shared.u64 t, %1; cvt.u32.u64 %0, t; }"
        : "=r"(a) : "l"(p));
    return a;
}
__device__ __forceinline__ uint32_t mapa_rank(uint32_t laddr, uint32_t rank) {
    uint32_t r;
    asm("mapa.shared::cluster.u32 %0, %1, %2;" : "=r"(r) : "r"(laddr), "r"(rank));
    return r;
}
__device__ __forceinline__ void st_remote_f32(uint32_t addr, float v) {
    asm volatile("st.shared::cluster.f32 [%0], %1;" :: "r"(addr), "f"(v) : "memory");
}
__device__ __forceinline__ void mbar_arrive_remote(uint32_t addr) {
    asm volatile("mbarrier.arrive.release.cluster.shared::cluster.b64 _, [%0];"
                 :: "r"(addr) : "memory");
}
__device__ __forceinline__ void mbar_init(uint32_t addr, uint32_t cnt) {
    asm volatile("mbarrier.init.shared.b64 [%0], %1;" :: "r"(addr), "r"(cnt) : "memory");
}
__device__ __forceinline__ void mbar_wait(uint32_t addr, uint32_t parity) {
    uint32_t done;
    do {
        asm volatile(
            "{\n\t.reg .pred p;\n\t"
            "mbarrier.try_wait.parity.acquire.cluster.shared::cta.b64 p, [%1], %2, 0x989680;\n\t"
            "selp.b32 %0, 1, 0, p;\n\t}"
            : "=r"(done) : "r"(addr), "r"(parity) : "memory");
    } while (!done);
}
__device__ __forceinline__ void cluster_sync_all() {
    asm volatile("barrier.cluster.arrive.aligned;" ::: "memory");
    asm volatile("barrier.cluster.wait.aligned;" ::: "memory");
}
__device__ __forceinline__ void bar_sync64(int id) {
    asm volatile("bar.sync %0, 64;" :: "r"(id) : "memory");
}

// scalar dot-32 over float4: 2 accumulators
#define DOT32(acc0, acc1, WP, AP)                                    \
    {                                                                \
        _Pragma("unroll")                                            \
        for (int q = 0; q < 8; q++) {                                \
            float4 x = (WP)[q], a = (AP)[q];                         \
            acc0 = fmaf(x.x, a.x, acc0); acc1 = fmaf(x.y, a.y, acc1);\
            acc0 = fmaf(x.z, a.z, acc0); acc1 = fmaf(x.w, a.w, acc1);\
        }                                                            \
    }

__global__ void __launch_bounds__(NTHREADS, 1) __cluster_dims__(RB, 1, 1)
nv_main_kernel(
    const float* __restrict__ z0,  const float* __restrict__ h0,
    const float* __restrict__ mean_w, const float* __restrict__ mean_b,
    const float* __restrict__ add_w,
    const float* __restrict__ gsw, const float* __restrict__ gsb_g,
    const float* __restrict__ gcw,
    const float* __restrict__ lw,  const float* __restrict__ lb_g,
    const float* __restrict__ ow,  const float* __restrict__ ob_g,
    const float* __restrict__ wih, const float* __restrict__ whh,
    const float* __restrict__ bih_g, const float* __restrict__ bhh_g,
    const int* __restrict__ src_idx, const int* __restrict__ tgt_idx,
    int T,
    float* __restrict__ zt, float* __restrict__ hf, float* __restrict__ ms)
{
    extern __shared__ char smraw[];
    SmemLayout& sm = *reinterpret_cast<SmemLayout*>(smraw);
    const int tid = threadIdx.x;
    const int g = blockIdx.x / RB;
    const int r = blockIdx.x % RB;
    const int b0 = g * NB_PER;

    // ---- incoming-edge list ----
    for (int e = tid; e < EB; e += NTHREADS) {
        if (tgt_idx[e] == r) {
            int s = src_idx[e];
            int slot = (s < r) ? s : s - 1;
            sm.elist[slot] = e;
            sm.slist[slot] = s;
        }
    }
    if (tid < NB_PER*2) mbar_init(smem_u32(&sm.mbar[tid >> 1][tid & 1]), 22);
    __syncthreads();

    // ---- cache weights ----
    for (int idx = tid; idx < 176*32; idx += NTHREADS) {
        int row = idx >> 5, k = idx & 31;
        int slot = row >> 4, m = row & 15;
        sm.mw2[row*36 + k] = mean_w[((size_t)sm.elist[slot]*MB + m)*LB + k];
    }
    for (int idx = tid; idx < 176; idx += NTHREADS) {
        int slot = idx >> 4, m = idx & 15;
        sm.mb[idx] = mean_b[sm.elist[slot]*MB + m];
    }
    for (int idx = tid; idx < 32*32; idx += NTHREADS) {
        int o = idx >> 5, i = idx & 31;
        sm.gsw2[o*36 + i] = gsw[((size_t)r*LB + o)*LB + i];
        sm.gcw2[o*36 + i] = gcw[((size_t)r*LB + o)*LB + i];
    }
    if (tid < 32) sm.gsb[tid] = gsb_g[r*LB + tid];
    for (int idx = tid; idx < 64*64; idx += NTHREADS) {
        int o = idx >> 6, i = idx & 63;
        sm.lw2[o*68 + i] = lw[((size_t)r*HFB + o)*(2*LB) + i];
    }
    if (tid < 64) sm.lbS[tid] = lb_g[r*HFB + tid];
    for (int idx = tid; idx < 32*64; idx += NTHREADS) {
        int l = idx >> 6, i = idx & 63;
        sm.ow2[l*68 + i] = ow[((size_t)r*LB + l)*HFB + i];
    }
    if (tid < 32) sm.obS[tid] = ob_g[r*LB + tid];
    for (int idx = tid; idx < 96*32; idx += NTHREADS) {
        int j = idx >> 5, i = idx & 31;
        sm.wih2[j*36 + i] = wih[((size_t)r*96 + j)*LB + i];
        sm.whh2[j*36 + i] = whh[((size_t)r*96 + j)*HHB + i];
    }
    if (tid < 96) { sm.bihS[tid] = bih_g[r*96 + tid]; sm.bhhS[tid] = bhh_g[r*96 + tid]; }

    // ---- init state ----
    for (int idx = tid; idx < NB_PER*RB*LB; idx += NTHREADS) {
        int bb = idx / (RB*LB); int rem = idx % (RB*LB);
        int rr = rem >> 5, i = rem & 31;
        sm.zsD[0][bb][rr][i] = z0[((size_t)(b0+bb)*RB + rr)*LB + i];
    }
    for (int idx = tid; idx < NB_PER*HHB; idx += NTHREADS) {
        int bb = idx >> 5, j = idx & 31;
        sm.hgS[bb][j] = h0[((size_t)(b0+bb)*RB + r)*HHB + j];
    }
    __syncthreads();   // mw2/mb/elist ready for C precompute

    // ---- precompute fused C = aw @ mw and binc = aw @ mb ----
    for (int idx = tid; idx < 352*32; idx += NTHREADS) {
        int row = idx >> 5, k = idx & 31;     // row = slot*32 + l
        int slot = row >> 5, l = row & 31;
        const float* awrow = add_w + ((size_t)sm.elist[slot]*LB + l)*MB;
        float acc = 0.f;
        #pragma unroll
        for (int m = 0; m < 16; m++)
            acc = fmaf(awrow[m], sm.mw2[(slot*16 + m)*36 + k], acc);
        sm.Cw[row*36 + k] = acc;
    }
    if (tid < 32) {
        float acc = 0.f;
        for (int slot = 0; slot < 11; slot++) {
            const float* awrow = add_w + ((size_t)sm.elist[slot]*LB + tid)*MB;
            #pragma unroll
            for (int m = 0; m < 16; m++)
                acc = fmaf(awrow[m], sm.mb[slot*16 + m], acc);
        }
        sm.bincS[tid] = acc;
    }
    __syncthreads();
    cluster_sync_all();

    const int w    = tid >> 5;          // 0..7
    const int lane = tid & 31;
    const int c    = w >> 1;            // team 0..3
    const int u    = w & 1;             // row-half within team
    const int pA   = 2*c, pB = 2*c + 1;
    const int q    = 2*c + u;           // this warp's own batch (post work)
    const int bh   = lane >> 4;         // batch-half of this lane
    const int p    = pA + bh;           // this lane's batch
    const int rr   = lane & 15;
    const int row0 = u*16 + rr;         // this lane's output row (0..31)
    const int rowB = row0 + 32;
    const int B1 = 1 + c, B2 = 5 + c, B3 = 9 + c;

    // ---- DSMEM deltas ----
    const uint32_t smem_base = smem_u32(smraw);
    uint32_t pdelta[11];
    #pragma unroll
    for (int k = 0; k < 11; k++) {
        uint32_t prank = (uint32_t)(k + (k >= r ? 1 : 0));
        pdelta[k] = mapa_rank(smem_base, prank) - smem_base;
    }
    uint32_t laneDelta = 0u;
    #pragma unroll
    for (int k = 0; k < 11; k++)
        if ((lane & 15) == k) laneDelta = pdelta[k];
    const uint32_t mbar_base = smem_u32(&sm.mbar[0][0]);
    const uint32_t mbar_pA = mbar_base + (uint32_t)(pA*16);
    const uint32_t mbar_pB = mbar_base + (uint32_t)(pB*16);
    const uint32_t mbar_ln = mbar_base + (uint32_t)(p*16);   // lane's batch

    // fixed per-lane weight pointers (chain: row0-based)
    const float4* wp_gsw  = (const float4*)&sm.gsw2[row0*36];
    const float4* wp_gcw  = (const float4*)&sm.gcw2[row0*36];
    const float4* wp_lw0a = (const float4*)&sm.lw2[row0*68];
    const float4* wp_lw1a = (const float4*)&sm.lw2[rowB*68];
    const float4* wp_lw0b = (const float4*)&sm.lw2[row0*68 + 32];
    const float4* wp_lw1b = (const float4*)&sm.lw2[rowB*68 + 32];
    const float4* wp_ow   = (const float4*)&sm.ow2[row0*68];
    // post (lane-based, full 32 rows of own batch q)
    const float4* w0h = (const float4*)&sm.whh2[(lane   )*36];
    const float4* w1h = (const float4*)&sm.whh2[(lane+32)*36];
    const float4* w2h = (const float4*)&sm.whh2[(lane+64)*36];
    const float4* w0i = (const float4*)&sm.wih2[(lane   )*36];
    const float4* w1i = (const float4*)&sm.wih2[(lane+32)*36];
    const float4* w2i = (const float4*)&sm.wih2[(lane+64)*36];
    // post means rows (R9 style): sub/m16 over own batch q
    const int sub = lane >> 4, m16 = lane & 15;
    int mrow_[6], msrc_[6];
    #pragma unroll
    for (int rd = 0; rd < 6; rd++) {
        int slot = 2*rd + sub;
        int slc = (slot < 11) ? slot : 10;
        mrow_[rd] = slc*16 + m16;
        msrc_[rd] = sm.slist[slc];
    }

    float hnew = 0.0f;
    int buf = 0;
    for (int t = 0; t < T; t++) {
        const int nxt = (buf == 2) ? 0 : buf + 1;

        // ---- S0: own-state dots (overlap peer wait) ----
        float4 za[8];
        {
            const float4* zp = (const float4*)&sm.zsD[buf][p][r][0];
            #pragma unroll
            for (int k = 0; k < 8; k++) za[k] = zp[k];
        }
        float gsv, lwz0, lwz1;
        {
            float a0 = sm.gsb[row0], a1 = 0.f;
            DOT32(a0, a1, wp_gsw, za);
            gsv = a0 + a1;
        }
        {
            float a0 = sm.lbS[row0], a1 = 0.f;
            DOT32(a0, a1, wp_lw0a, za);
            lwz0 = a0 + a1;
        }
        {
            float a0 = sm.lbS[rowB], a1 = 0.f;
            DOT32(a0, a1, wp_lw1a, za);
            lwz1 = a0 + a1;
        }

        // ---- wait peers' z(t-1): both team batch chains ----
        if (t > 0) {
            const uint32_t off = (uint32_t)(((t - 1) & 1) * 8);
            const uint32_t par = (uint32_t)(((t - 1) >> 1) & 1);
            mbar_wait(mbar_pA + off, par);
            mbar_wait(mbar_pB + off, par);
        }

        // ---- S1: fused inc = binc + C·z (11 independent dot-32s) ----
        {
            float a0 = sm.bincS[row0], a1=0.f,a2=0.f,a3=0.f,a4=0.f,a5=0.f,a6=0.f,a7=0.f;
            #pragma unroll
            for (int sl = 0; sl < 11; sl++) {
                const float4* wpj = (const float4*)&sm.Cw[(sl*32 + row0)*36];
                const float4* apj = (const float4*)&sm.zsD[buf][p][sm.slist[sl]][0];
                #pragma unroll
                for (int k2 = 0; k2 < 4; k2++) {
                    float4 x0 = wpj[2*k2],   v0 = apj[2*k2];
                    float4 x1 = wpj[2*k2+1], v1 = apj[2*k2+1];
                    a0 = fmaf(x0.x, v0.x, a0); a1 = fmaf(x0.y, v0.y, a1);
                    a2 = fmaf(x0.z, v0.z, a2); a3 = fmaf(x0.w, v0.w, a3);
                    a4 = fmaf(x1.x, v1.x, a4); a5 = fmaf(x1.y, v1.y, a5);
                    a6 = fmaf(x1.z, v1.z, a6); a7 = fmaf(x1.w, v1.w, a7);
                }
            }
            sm.incD[buf][p][row0] = ((a0 + a1) + (a2 + a3)) + ((a4 + a5) + (a6 + a7));
        }
        bar_sync64(B1);     // inc complete (both halves)

        // ---- S2: gate + hidden halves ----
        float gate;
        {
            float4 ia[8];
            const float4* ip = (const float4*)&sm.incD[buf][p][0];
            #pragma unroll
            for (int k = 0; k < 8; k++) ia[k] = ip[k];

            float a0 = gsv, a1 = 0.f;
            DOT32(a0, a1, wp_gcw, ia);
            gate = fsig(a0 + a1);

            float b0v = lwz0, b1 = 0.f;
            DOT32(b0v, b1, wp_lw0b, ia);
            const float v0 = b0v + b1;
            sm.hbufT[p][row0] = v0 * fsig(v0);

            float c0 = lwz1, c1 = 0.f;
            DOT32(c0, c1, wp_lw1b, ia);
            const float v1 = c0 + c1;
            sm.hbufT[p][rowB] = v1 * fsig(v1);
        }
        bar_sync64(B2);     // hbuf complete

        // ---- S3: out layer + z update + publish ----
        {
            const float4* ap = (const float4*)&sm.hbufT[p][0];
            float a0 = sm.obS[row0], a1 = 0.f, a2 = 0.f, a3 = 0.f;
            #pragma unroll
            for (int k = 0; k < 16; k++) {
                float4 x = wp_ow[k], a = ap[k];
                a0 = fmaf(x.x, a.x, a0); a1 = fmaf(x.y, a.y, a1);
                a2 = fmaf(x.z, a.z, a2); a3 = fmaf(x.w, a.w, a3);
            }
            const float target = tanhf((a0 + a1) + (a2 + a3));
            const float zold = sm.zsD[buf][p][r][row0];
            const float znew = fmaf(0.1f * gate, target - zold, zold);

            sm.zsD[nxt][p][r][row0] = znew;
            const uint32_t zaddr = smem_base +
                (uint32_t)((const char*)&sm.zsD[nxt][p][r][row0] - (const char*)&sm);
            #pragma unroll
            for (int k = 0; k < 11; k++)
                st_remote_f32(zaddr + pdelta[k], znew);
            __syncwarp();
            if ((lane & 15) < 11)
                mbar_arrive_remote(mbar_ln + (uint32_t)((t & 1) * 8) + laneDelta);
            // off-chain store
            zt[(((size_t)(b0 + p)*T + t)*RB + r)*LB + row0] = znew;
        }
        bar_sync64(B3);     // local zsD[nxt] rows complete for next S0

        // ---- POST (off inter-CTA chain): GRU + means + ms store, own batch q ----
        {
            // GRU
            float gh0, gh1, gh2;
            {
                const float4* hp = (const float4*)&sm.hgS[q][0];
                float4 ha[8];
                #pragma unroll
                for (int k = 0; k < 8; k++) ha[k] = hp[k];
                float a0 = sm.bhhS[lane],    a1 = 0.f;
                float b0v = sm.bhhS[lane+32], b1 = 0.f;
                float c0 = sm.bhhS[lane+64], c1 = 0.f;
                DOT32(a0, a1, w0h, ha);
                DOT32(b0v, b1, w1h, ha);
                DOT32(c0, c1, w2h, ha);
                gh0 = a0 + a1; gh1 = b0v + b1; gh2 = c0 + c1;
            }
            {
                const float4* ip = (const float4*)&sm.incD[buf][q][0];
                float4 ia[8];
                #pragma unroll
                for (int k = 0; k < 8; k++) ia[k] = ip[k];
                float g0a = sm.bihS[lane],    g0b = 0.f;
                float g1a = sm.bihS[lane+32], g1b = 0.f;
                float g2a = sm.bihS[lane+64], g2b = 0.f;
                DOT32(g0a, g0b, w0i, ia);
                DOT32(g1a, g1b, w1i, ia);
                DOT32(g2a, g2b, w2i, ia);
                const float gr = fsig((g0a + g0b) + gh0);
                const float gz = fsig((g1a + g1b) + gh1);
                const float nn = tanhf(fmaf(gr, gh2, g2a + g2b));
                const float hold = sm.hgS[q][lane];
                hnew = (1.0f - gz)*nn + gz*hold;
                sm.hgS[q][lane] = hnew;
            }
            __syncwarp();
            // means for ms output (batch q), straight to global
            float* msrow = ms + ((size_t)(b0 + q)*T + t)*(EB*MB);
            #pragma unroll
            for (int rd = 0; rd < 6; rd++) {
                if (2*rd + sub < 11) {
                    const float4* wp = (const float4*)&sm.mw2[mrow_[rd]*36];
                    const float4* ap = (const float4*)&sm.zsD[buf][q][msrc_[rd]][0];
                    float a0 = sm.mb[mrow_[rd]], a1 = 0.f;
                    DOT32(a0, a1, wp, ap);
                    msrow[sm.elist[mrow_[rd] >> 4]*MB + (mrow_[rd] & 15)] = a0 + a1;
                }
            }
        }

        buf = nxt;
    }

    hf[((size_t)(b0 + q)*RB + r)*HHB + lane] = hnew;

    cluster_sync_all();   // peers may still be writing our smem
}

extern "C" void kernel_launch(void* const* d_in, const int* in_sizes, int n_in,
                              void* d_out, int out_size) {
    const float* z0     = (const float*)d_in[0];
    const float* h0     = (const float*)d_in[1];
    const float* mean_w = (const float*)d_in[2];
    const float* mean_b = (const float*)d_in[3];
    const float* add_w  = (const float*)d_in[4];
    const float* gsw    = (const float*)d_in[5];
    const float* gsb    = (const float*)d_in[6];
    const float* gcw    = (const float*)d_in[7];
    const float* lw     = (const float*)d_in[8];
    const float* lb     = (const float*)d_in[9];
    const float* ow     = (const float*)d_in[10];
    const float* ob     = (const float*)d_in[11];
    const float* wih    = (const float*)d_in[12];
    const float* whh    = (const float*)d_in[13];
    const float* bih    = (const float*)d_in[14];
    const float* bhh    = (const float*)d_in[15];
    const int* src_idx  = (const int*)d_in[16];
    const int* tgt_idx  = (const int*)d_in[17];
    // out_size = B*T*R*L + B*R*Hh + B*T*E*M
    const int per_t = BTOT*RB*LB + BTOT*EB*MB;
    const int T = (out_size - BTOT*RB*HHB) / per_t;

    float* out = (float*)d_out;
    float* zt = out;
    float* hf = zt + (size_t)BTOT * T * RB * LB;
    float* ms = hf + (size_t)BTOT * RB * HHB;

    cudaFuncSetAttribute(nv_main_kernel,
                         cudaFuncAttributeMaxDynamicSharedMemorySize,
                         (int)sizeof(SmemLayout));
    cudaFuncSetAttribute(nv_main_kernel,
                         cudaFuncAttributeNonPortableClusterSizeAllowed, 1);

    nv_main_kernel<<<NBLOCKS, NTHREADS, sizeof(SmemLayout)>>>(
        z0, h0, mean_w, mean_b, add_w, gsw, gsb, gcw, lw, lb, ow, ob,
        wih, whh, bih, bhh, src_idx, tgt_idx, T, zt, hf, ms);
}